// round 10
// baseline (speedup 1.0000x reference)
#include <cuda_runtime.h>
#include <cuda_bf16.h>
#include <cstdint>
#include <math.h>

#define T  1024
#define H  1024
#define II 2816
#define E  8

__device__ int   g_expert_id[T];
__device__ int   g_counts[E];
__device__ int   g_offsets[E + 1];
__device__ int   g_cursor[E];
__device__ int   g_token_list[T];
__device__ __nv_bfloat16 g_xh[(size_t)T * H];
__device__ __nv_bfloat16 g_xl[(size_t)T * H];
__device__ __nv_bfloat16 g_ah[(size_t)(T + 128) * II];
__device__ __nv_bfloat16 g_al[(size_t)(T + 128) * II];

// ---------- helpers ----------
__device__ __forceinline__ uint32_t smem_u32(const void* p) {
    uint32_t a;
    asm("{ .reg .u64 t; cvta.to.shared.u64 t, %1; cvt.u32.u64 %0, t; }" : "=r"(a) : "l"(p));
    return a;
}
__device__ __forceinline__ uint32_t swz(uint32_t o) { return o ^ ((o >> 3) & 0x70); }

#define CP16(d, s) asm volatile("cp.async.cg.shared.global [%0], [%1], 16;" :: "r"(d), "l"(s) : "memory")
#define CPC()      asm volatile("cp.async.commit_group;" ::: "memory")
#define CPW(n)     asm volatile("cp.async.wait_group %0;" :: "n"(n) : "memory")

__device__ __forceinline__ void ldm4(uint32_t* r, uint32_t a) {
    asm volatile("ldmatrix.sync.aligned.m8n8.x4.shared.b16 {%0,%1,%2,%3}, [%4];"
        : "=r"(r[0]), "=r"(r[1]), "=r"(r[2]), "=r"(r[3]) : "r"(a));
}
__device__ __forceinline__ void mma16(float* c, const uint32_t* a, const uint32_t* b) {
    asm volatile("mma.sync.aligned.m16n8k16.row.col.f32.bf16.bf16.f32 "
        "{%0,%1,%2,%3}, {%4,%5,%6,%7}, {%8,%9}, {%0,%1,%2,%3};"
        : "+f"(c[0]), "+f"(c[1]), "+f"(c[2]), "+f"(c[3])
        : "r"(a[0]), "r"(a[1]), "r"(a[2]), "r"(a[3]), "r"(b[0]), "r"(b[1]));
}
__device__ __forceinline__ uint32_t b2u(__nv_bfloat162 v) { return *(uint32_t*)&v; }
__device__ __forceinline__ void sts4u(uint32_t a, uint32_t x, uint32_t y, uint32_t z, uint32_t w) {
    asm volatile("st.shared.v4.b32 [%0], {%1, %2, %3, %4};"
        :: "r"(a), "r"(x), "r"(y), "r"(z), "r"(w) : "memory");
}
__device__ __forceinline__ void cvt8_sts(uint32_t dhi, uint32_t dlo, float4 a, float4 b) {
    __nv_bfloat162 h0 = __floats2bfloat162_rn(a.x, a.y);
    __nv_bfloat162 h1 = __floats2bfloat162_rn(a.z, a.w);
    __nv_bfloat162 h2 = __floats2bfloat162_rn(b.x, b.y);
    __nv_bfloat162 h3 = __floats2bfloat162_rn(b.z, b.w);
    sts4u(dhi, b2u(h0), b2u(h1), b2u(h2), b2u(h3));
    __nv_bfloat162 l0 = __floats2bfloat162_rn(a.x - __bfloat162float(h0.x), a.y - __bfloat162float(h0.y));
    __nv_bfloat162 l1 = __floats2bfloat162_rn(a.z - __bfloat162float(h1.x), a.w - __bfloat162float(h1.y));
    __nv_bfloat162 l2 = __floats2bfloat162_rn(b.x - __bfloat162float(h2.x), b.y - __bfloat162float(h2.y));
    __nv_bfloat162 l3 = __floats2bfloat162_rn(b.z - __bfloat162float(h3.x), b.w - __bfloat162float(h3.y));
    sts4u(dlo, b2u(l0), b2u(l1), b2u(l2), b2u(l3));
}

// ---------- routing (router + x split fused) ----------
__global__ void zero_kernel() {
    int i = threadIdx.x;
    if (i < E) { g_counts[i] = 0; g_cursor[i] = 0; }
}
__global__ void router_kernel(const float* __restrict__ x, const float* __restrict__ rw) {
    int t = blockIdx.x;
    __shared__ float sx[H];
    for (int i = threadIdx.x; i < H; i += blockDim.x) sx[i] = x[(size_t)t * H + i];
    __syncthreads();
    int w = threadIdx.x >> 5, l = threadIdx.x & 31;
    const float* wr = rw + (size_t)w * H;
    float acc = 0.f;
    for (int i = l; i < H; i += 32) acc += sx[i] * wr[i];
#pragma unroll
    for (int o = 16; o > 0; o >>= 1) acc += __shfl_xor_sync(0xffffffffu, acc, o);
    __shared__ float logits[E];
    if (l == 0) logits[w] = acc;
    __syncthreads();
    if (threadIdx.x == 0) {
        int best = 0; float bv = logits[0];
#pragma unroll
        for (int e = 1; e < E; e++) if (logits[e] > bv) { bv = logits[e]; best = e; }
        g_expert_id[t] = best;
        atomicAdd(&g_counts[best], 1);
    }
    // fused x -> bf16 hi/lo split (row already in smem)
    int i = threadIdx.x * 4;
    float4 v = *(float4*)&sx[i];
    __nv_bfloat162 h01 = __floats2bfloat162_rn(v.x, v.y);
    __nv_bfloat162 h23 = __floats2bfloat162_rn(v.z, v.w);
    size_t base = (size_t)t * H + i;
    *(__nv_bfloat162*)(g_xh + base) = h01;
    *(__nv_bfloat162*)(g_xh + base + 2) = h23;
    __nv_bfloat162 l01 = __floats2bfloat162_rn(v.x - __bfloat162float(h01.x), v.y - __bfloat162float(h01.y));
    __nv_bfloat162 l23 = __floats2bfloat162_rn(v.z - __bfloat162float(h23.x), v.w - __bfloat162float(h23.y));
    *(__nv_bfloat162*)(g_xl + base) = l01;
    *(__nv_bfloat162*)(g_xl + base + 2) = l23;
}
__global__ void scan_scatter_kernel() {
    if (threadIdx.x == 0) {
        int o = 0;
        for (int e = 0; e < E; e++) { g_offsets[e] = o; o += g_counts[e]; }
        g_offsets[E] = o;
    }
    __syncthreads();
    int t = threadIdx.x;
    int e = g_expert_id[t];
    g_token_list[g_offsets[e] + atomicAdd(&g_cursor[e], 1)] = t;
}

// ---------- GEMM1: act = silu(X Wg^T) * (X Wu^T) ----------
// CTA: 128 tokens x 64 i-cols (gate/up rows interleaved -> MMA-N = 128).
// 3 smem stages of 32KB (A 16KB hi|lo + B 16KB); weight LDG prefetch distance 2.
#define G1_SMEM (1024 + 3 * 32768)
__global__ __launch_bounds__(256, 1)
void gemm1_kernel(const float* __restrict__ gw, const float* __restrict__ uw) {
    extern __shared__ __align__(1024) char smem[];
    uint32_t sb = smem_u32(smem);
    int tid = threadIdx.x, lane = tid & 31, wid = tid >> 5;
    int e = blockIdx.z;
    int off = g_offsets[e];
    int n = g_offsets[e + 1] - off;
    int t0 = blockIdx.y * 128;
    if (t0 >= n) return;
    int i0 = blockIdx.x * 64;
    const float* gwe = gw + (size_t)e * II * H;
    const float* uwe = uw + (size_t)e * II * H;
    int* sTok = (int*)(smem + 32);
    if (tid < 128) {
        int gm = t0 + tid;
        sTok[tid] = (gm < n) ? g_token_list[off + gm] : g_token_list[off];
    }
    __syncthreads();

    float C[2][8][4];
#pragma unroll
    for (int a = 0; a < 2; a++)
#pragma unroll
        for (int b = 0; b < 8; b++)
#pragma unroll
            for (int c = 0; c < 4; c++) C[a][b][c] = 0.f;

#define G1_ST(st) (sb + 1024 + (uint32_t)(st) * 32768)

#define G1_CPA(ch, st) do { \
    uint32_t bufA = G1_ST(st); \
    _Pragma("unroll") \
    for (int it = 0; it < 4; it++) { \
        int idx = tid + it * 256; \
        int row = idx >> 3, cc = idx & 7; \
        const __nv_bfloat16* src = ((cc < 4) ? g_xh : g_xl) \
            + (size_t)sTok[row] * H + (ch) * 32 + (cc & 3) * 8; \
        CP16(bufA + swz((uint32_t)(row * 128 + cc * 16)), src); \
    } \
    CPC(); \
} while (0)

#define G1_LDGW(ch, s) do { \
    _Pragma("unroll") \
    for (int it = 0; it < 2; it++) { \
        int idx = tid + it * 256; \
        int row = idx >> 2, q = idx & 3; \
        const float* src = ((row & 1) ? uwe : gwe) + (size_t)(i0 + (row >> 1)) * H + (ch) * 32 + q * 8; \
        wv[s][it][0] = *(const float4*)src; \
        wv[s][it][1] = *(const float4*)(src + 4); \
    } \
} while (0)

#define G1_STSW(s, st) do { \
    uint32_t bufB = G1_ST(st) + 16384; \
    _Pragma("unroll") \
    for (int it = 0; it < 2; it++) { \
        int idx = tid + it * 256; \
        int row = idx >> 2, q = idx & 3; \
        cvt8_sts(bufB + swz((uint32_t)(row * 128 + q * 16)), \
                 bufB + swz((uint32_t)(row * 128 + 64 + q * 16)), \
                 wv[s][it][0], wv[s][it][1]); \
    } \
} while (0)

    float4 wv[2][2][2];
    int wm0 = (wid & 3) * 32, wn0 = (wid >> 2) * 64;

    // preamble: stages 0,1 fully staged; chunk 2 weights in regs
    G1_CPA(0, 0); G1_CPA(1, 1);
    G1_LDGW(0, 0); G1_STSW(0, 0);
    G1_LDGW(1, 1); G1_STSW(1, 1);
    G1_LDGW(2, 0);

    const int NC = H / 32;
    for (int c = 0; c < NC; c++) {
        int st = c % 3;
        if (c + 2 < NC) G1_CPA(c + 2, (c + 2) % 3);
        if (c + 3 < NC) G1_LDGW(c + 3, (c + 3) & 1);
        if (c + 2 < NC) G1_STSW((c + 2) & 1, (c + 2) % 3);
        if (c + 2 < NC)      CPW(2);
        else if (c + 1 < NC) CPW(1);
        else                 CPW(0);
        __syncthreads();

        uint32_t bufA = G1_ST(st);
        uint32_t bufB = bufA + 16384;
#pragma unroll
        for (int ks = 0; ks < 2; ks++) {
            uint32_t ah[2][4], al[2][4];
            int krow = lane & 15, kc = ks * 16 + ((lane >> 4) & 1) * 8;
#pragma unroll
            for (int mt = 0; mt < 2; mt++) {
                uint32_t offh = (uint32_t)((wm0 + mt * 16 + krow) * 128 + kc * 2);
                ldm4(ah[mt], bufA + swz(offh));
                ldm4(al[mt], bufA + swz(offh + 64));
            }
#pragma unroll
            for (int nt2 = 0; nt2 < 4; nt2++) {
                int brow = wn0 + nt2 * 16 + ((lane >> 4) & 1) * 8 + (lane & 7);
                int bkc = ks * 16 + ((lane >> 3) & 1) * 8;
                uint32_t offb = (uint32_t)(brow * 128 + bkc * 2);
                uint32_t bh[4], bl[4];
                ldm4(bh, bufB + swz(offb));
                ldm4(bl, bufB + swz(offb + 64));
#pragma unroll
                for (int mt = 0; mt < 2; mt++) {
                    mma16(C[mt][nt2 * 2],     ah[mt], bh);
                    mma16(C[mt][nt2 * 2 + 1], ah[mt], bh + 2);
                    mma16(C[mt][nt2 * 2],     ah[mt], bl);
                    mma16(C[mt][nt2 * 2 + 1], ah[mt], bl + 2);
                    mma16(C[mt][nt2 * 2],     al[mt], bh);
                    mma16(C[mt][nt2 * 2 + 1], al[mt], bh + 2);
                }
            }
        }
        __syncthreads();
    }

    // epilogue: c0 = gate, c1 = up -> silu(g)*u -> bf16 hi/lo
    int tq = lane >> 2, tr = lane & 3;
#pragma unroll
    for (int mt = 0; mt < 2; mt++)
#pragma unroll
        for (int nt = 0; nt < 8; nt++) {
            int col = i0 + (wn0 >> 1) + nt * 4 + tr;
#pragma unroll
            for (int hh = 0; hh < 2; hh++) {
                int gm = t0 + wm0 + mt * 16 + tq + hh * 8;
                if (gm < n) {
                    float g = C[mt][nt][hh * 2], u = C[mt][nt][hh * 2 + 1];
                    float a = g / (1.f + __expf(-g)) * u;
                    __nv_bfloat16 h = __float2bfloat16_rn(a);
                    size_t ix = (size_t)(off + gm) * II + col;
                    g_ah[ix] = h;
                    g_al[ix] = __float2bfloat16_rn(a - __bfloat162float(h));
                }
            }
        }
}

// ---------- GEMM2: out[token] = act @ Wd^T ----------
// CTA: 128 tokens x 64 h-cols. 3 stages of 24KB (A 16KB + B 8KB).
#define G2_SMEM (1024 + 3 * 24576)
__global__ __launch_bounds__(256, 1)
void gemm2_kernel(const float* __restrict__ dw, float* __restrict__ out) {
    extern __shared__ __align__(1024) char smem[];
    uint32_t sb = smem_u32(smem);
    int tid = threadIdx.x, lane = tid & 31, wid = tid >> 5;
    int e = blockIdx.z;
    int off = g_offsets[e];
    int n = g_offsets[e + 1] - off;
    int t0 = blockIdx.y * 128;
    if (t0 >= n) return;
    int h0 = blockIdx.x * 64;
    const float* dwe = dw + (size_t)e * H * II;
    int* sTok = (int*)(smem + 32);
    if (tid < 128) {
        int gm = t0 + tid;
        sTok[tid] = (gm < n) ? g_token_list[off + gm] : 0;
    }
    __syncthreads();

    float C[2][4][4];
#pragma unroll
    for (int a = 0; a < 2; a++)
#pragma unroll
        for (int b = 0; b < 4; b++)
#pragma unroll
            for (int c = 0; c < 4; c++) C[a][b][c] = 0.f;

#define G2_ST(st) (sb + 1024 + (uint32_t)(st) * 24576)

#define G2_CPA(ch, st) do { \
    uint32_t bufA = G2_ST(st); \
    _Pragma("unroll") \
    for (int it = 0; it < 4; it++) { \
        int idx = tid + it * 256; \
        int row = idx >> 3, cc = idx & 7; \
        const __nv_bfloat16* src = ((cc < 4) ? g_ah : g_al) \
            + (size_t)(off + t0 + row) * II + (ch) * 32 + (cc & 3) * 8; \
        CP16(bufA + swz((uint32_t)(row * 128 + cc * 16)), src); \
    } \
    CPC(); \
} while (0)

#define G2_LDGW(ch, s) do { \
    int row = tid >> 2, q = tid & 3; \
    const float* src = dwe + (size_t)(h0 + row) * II + (ch) * 32 + q * 8; \
    wv[s][0] = *(const float4*)src; \
    wv[s][1] = *(const float4*)(src + 4); \
} while (0)

#define G2_STSW(s, st) do { \
    uint32_t bufB = G2_ST(st) + 16384; \
    int row = tid >> 2, q = tid & 3; \
    cvt8_sts(bufB + swz((uint32_t)(row * 128 + q * 16)), \
             bufB + swz((uint32_t)(row * 128 + 64 + q * 16)), \
             wv[s][0], wv[s][1]); \
} while (0)

    float4 wv[2][2];
    int wm0 = (wid & 3) * 32, wn0 = (wid >> 2) * 32;

    G2_CPA(0, 0); G2_CPA(1, 1);
    G2_LDGW(0, 0); G2_STSW(0, 0);
    G2_LDGW(1, 1); G2_STSW(1, 1);
    G2_LDGW(2, 0);

    const int NC = II / 32;
    for (int c = 0; c < NC; c++) {
        int st = c % 3;
        if (c + 2 < NC) G2_CPA(c + 2, (c + 2) % 3);
        if (c + 3 < NC) G2_LDGW(c + 3, (c + 3) & 1);
        if (c + 2 < NC) G2_STSW((c + 2) & 1, (c + 2) % 3);
        if (c + 2 < NC)      CPW(2);
        else if (c + 1 < NC) CPW(1);
        else                 CPW(0);
        __syncthreads();

        uint32_t bufA = G2_ST(st);
        uint32_t bufB = bufA + 16384;
#pragma unroll
        for (int ks = 0; ks < 2; ks++) {
            uint32_t ah[2][4], al[2][4];
            int krow = lane & 15, kc = ks * 16 + ((lane >> 4) & 1) * 8;
#pragma unroll
            for (int mt = 0; mt < 2; mt++) {
                uint32_t offh = (uint32_t)((wm0 + mt * 16 + krow) * 128 + kc * 2);
                ldm4(ah[mt], bufA + swz(offh));
                ldm4(al[mt], bufA + swz(offh + 64));
            }
#pragma unroll
            for (int nt2 = 0; nt2 < 2; nt2++) {
                int brow = wn0 + nt2 * 16 + ((lane >> 4) & 1) * 8 + (lane & 7);
                int bkc = ks * 16 + ((lane >> 3) & 1) * 8;
                uint32_t offb = (uint32_t)(brow * 128 + bkc * 2);
                uint32_t bh[4], bl[4];
                ldm4(bh, bufB + swz(offb));
                ldm4(bl, bufB + swz(offb + 64));
#pragma unroll
                for (int mt = 0; mt < 2; mt++) {
                    mma16(C[mt][nt2 * 2],     ah[mt], bh);
                    mma16(C[mt][nt2 * 2 + 1], ah[mt], bh + 2);
                    mma16(C[mt][nt2 * 2],     ah[mt], bl);
                    mma16(C[mt][nt2 * 2 + 1], ah[mt], bl + 2);
                    mma16(C[mt][nt2 * 2],     al[mt], bh);
                    mma16(C[mt][nt2 * 2 + 1], al[mt], bh + 2);
                }
            }
        }
        __syncthreads();
    }

    int tq = lane >> 2, tr = lane & 3;
#pragma unroll
    for (int mt = 0; mt < 2; mt++)
#pragma unroll
        for (int nt = 0; nt < 4; nt++) {
            int col = h0 + wn0 + nt * 8 + tr * 2;
#pragma unroll
            for (int hh = 0; hh < 2; hh++) {
                int m = wm0 + mt * 16 + tq + hh * 8;
                int gm = t0 + m;
                if (gm < n) {
                    int tok = sTok[m];
                    float2 o = make_float2(C[mt][nt][hh * 2], C[mt][nt][hh * 2 + 1]);
                    *(float2*)(out + (size_t)tok * H + col) = o;
                }
            }
        }
}

// ---------- launch ----------
extern "C" void kernel_launch(void* const* d_in, const int* in_sizes, int n_in,
                              void* d_out, int out_size) {
    const float* x  = (const float*)d_in[0];
    const float* rw = (const float*)d_in[1];
    const float* gw = (const float*)d_in[2];
    const float* uw = (const float*)d_in[3];
    const float* dw = (const float*)d_in[4];
    float* out = (float*)d_out;

    cudaFuncSetAttribute(gemm1_kernel, cudaFuncAttributeMaxDynamicSharedMemorySize, G1_SMEM);
    cudaFuncSetAttribute(gemm2_kernel, cudaFuncAttributeMaxDynamicSharedMemorySize, G2_SMEM);

    zero_kernel<<<1, 32>>>();
    router_kernel<<<T, 256>>>(x, rw);
    scan_scatter_kernel<<<1, 1024>>>();
    gemm1_kernel<<<dim3(II / 64, T / 128, E), 256, G1_SMEM>>>(gw, uw);
    gemm2_kernel<<<dim3(H / 64, T / 128, E), 256, G2_SMEM>>>(dw, out);
}

// round 11
// speedup vs baseline: 1.1561x; 1.1561x over previous
#include <cuda_runtime.h>
#include <cuda_bf16.h>
#include <cstdint>
#include <math.h>

#define T  1024
#define H  1024
#define II 2816
#define E  8

__device__ int   g_expert_id[T];
__device__ int   g_counts[E];
__device__ int   g_offsets[E + 1];
__device__ int   g_cursor[E];
__device__ int   g_token_list[T];
__device__ __nv_bfloat16 g_xh[(size_t)T * H];
__device__ __nv_bfloat16 g_xl[(size_t)T * H];
__device__ __nv_bfloat16 g_ah[(size_t)(T + 128) * II];
__device__ __nv_bfloat16 g_al[(size_t)(T + 128) * II];

// ---------- helpers ----------
__device__ __forceinline__ uint32_t smem_u32(const void* p) {
    uint32_t a;
    asm("{ .reg .u64 t; cvta.to.shared.u64 t, %1; cvt.u32.u64 %0, t; }" : "=r"(a) : "l"(p));
    return a;
}
__device__ __forceinline__ uint32_t swz(uint32_t o) { return o ^ ((o >> 3) & 0x70); }

#define CP16(d, s) asm volatile("cp.async.cg.shared.global [%0], [%1], 16;" :: "r"(d), "l"(s) : "memory")
#define CPC()      asm volatile("cp.async.commit_group;" ::: "memory")
#define CPW(n)     asm volatile("cp.async.wait_group %0;" :: "n"(n) : "memory")

__device__ __forceinline__ void ldm4(uint32_t* r, uint32_t a) {
    asm volatile("ldmatrix.sync.aligned.m8n8.x4.shared.b16 {%0,%1,%2,%3}, [%4];"
        : "=r"(r[0]), "=r"(r[1]), "=r"(r[2]), "=r"(r[3]) : "r"(a));
}
__device__ __forceinline__ void mma16(float* c, const uint32_t* a, const uint32_t* b) {
    asm volatile("mma.sync.aligned.m16n8k16.row.col.f32.bf16.bf16.f32 "
        "{%0,%1,%2,%3}, {%4,%5,%6,%7}, {%8,%9}, {%0,%1,%2,%3};"
        : "+f"(c[0]), "+f"(c[1]), "+f"(c[2]), "+f"(c[3])
        : "r"(a[0]), "r"(a[1]), "r"(a[2]), "r"(a[3]), "r"(b[0]), "r"(b[1]));
}
__device__ __forceinline__ uint32_t b2u(__nv_bfloat162 v) { return *(uint32_t*)&v; }
__device__ __forceinline__ void sts4u(uint32_t a, uint32_t x, uint32_t y, uint32_t z, uint32_t w) {
    asm volatile("st.shared.v4.b32 [%0], {%1, %2, %3, %4};"
        :: "r"(a), "r"(x), "r"(y), "r"(z), "r"(w) : "memory");
}
__device__ __forceinline__ void cvt8_sts(uint32_t dhi, uint32_t dlo, float4 a, float4 b) {
    __nv_bfloat162 h0 = __floats2bfloat162_rn(a.x, a.y);
    __nv_bfloat162 h1 = __floats2bfloat162_rn(a.z, a.w);
    __nv_bfloat162 h2 = __floats2bfloat162_rn(b.x, b.y);
    __nv_bfloat162 h3 = __floats2bfloat162_rn(b.z, b.w);
    sts4u(dhi, b2u(h0), b2u(h1), b2u(h2), b2u(h3));
    __nv_bfloat162 l0 = __floats2bfloat162_rn(a.x - __bfloat162float(h0.x), a.y - __bfloat162float(h0.y));
    __nv_bfloat162 l1 = __floats2bfloat162_rn(a.z - __bfloat162float(h1.x), a.w - __bfloat162float(h1.y));
    __nv_bfloat162 l2 = __floats2bfloat162_rn(b.x - __bfloat162float(h2.x), b.y - __bfloat162float(h2.y));
    __nv_bfloat162 l3 = __floats2bfloat162_rn(b.z - __bfloat162float(h3.x), b.w - __bfloat162float(h3.y));
    sts4u(dlo, b2u(l0), b2u(l1), b2u(l2), b2u(l3));
}

// ---------- routing (router + x split fused) ----------
__global__ void zero_kernel() {
    int i = threadIdx.x;
    if (i < E) { g_counts[i] = 0; g_cursor[i] = 0; }
}
__global__ void router_kernel(const float* __restrict__ x, const float* __restrict__ rw) {
    int t = blockIdx.x;
    __shared__ float sx[H];
    for (int i = threadIdx.x; i < H; i += blockDim.x) sx[i] = x[(size_t)t * H + i];
    __syncthreads();
    int w = threadIdx.x >> 5, l = threadIdx.x & 31;
    const float* wr = rw + (size_t)w * H;
    float acc = 0.f;
    for (int i = l; i < H; i += 32) acc += sx[i] * wr[i];
#pragma unroll
    for (int o = 16; o > 0; o >>= 1) acc += __shfl_xor_sync(0xffffffffu, acc, o);
    __shared__ float logits[E];
    if (l == 0) logits[w] = acc;
    __syncthreads();
    if (threadIdx.x == 0) {
        int best = 0; float bv = logits[0];
#pragma unroll
        for (int e = 1; e < E; e++) if (logits[e] > bv) { bv = logits[e]; best = e; }
        g_expert_id[t] = best;
        atomicAdd(&g_counts[best], 1);
    }
    int i = threadIdx.x * 4;
    float4 v = *(float4*)&sx[i];
    __nv_bfloat162 h01 = __floats2bfloat162_rn(v.x, v.y);
    __nv_bfloat162 h23 = __floats2bfloat162_rn(v.z, v.w);
    size_t base = (size_t)t * H + i;
    *(__nv_bfloat162*)(g_xh + base) = h01;
    *(__nv_bfloat162*)(g_xh + base + 2) = h23;
    __nv_bfloat162 l01 = __floats2bfloat162_rn(v.x - __bfloat162float(h01.x), v.y - __bfloat162float(h01.y));
    __nv_bfloat162 l23 = __floats2bfloat162_rn(v.z - __bfloat162float(h23.x), v.w - __bfloat162float(h23.y));
    *(__nv_bfloat162*)(g_xl + base) = l01;
    *(__nv_bfloat162*)(g_xl + base + 2) = l23;
}
__global__ void scan_scatter_kernel() {
    if (threadIdx.x == 0) {
        int o = 0;
        for (int e = 0; e < E; e++) { g_offsets[e] = o; o += g_counts[e]; }
        g_offsets[E] = o;
    }
    __syncthreads();
    int t = threadIdx.x;
    int e = g_expert_id[t];
    g_token_list[g_offsets[e] + atomicAdd(&g_cursor[e], 1)] = t;
}

// ---------- GEMM1: act = silu(X Wg^T) * (X Wu^T) ----------
// CTA: 128 tokens x 32 i-cols (gate/up rows interleaved -> MMA-N = 64).
// 2 smem stages of 24KB (A 16KB hi|lo + B 8KB). Warp tile 32x32 (4M x 2N warps).
#define G1_STAGE 24576
#define G1_SMEM (1024 + 2 * G1_STAGE)
__global__ __launch_bounds__(256, 2)
void gemm1_kernel(const float* __restrict__ gw, const float* __restrict__ uw) {
    extern __shared__ __align__(1024) char smem[];
    uint32_t sb = smem_u32(smem);
    int tid = threadIdx.x, lane = tid & 31, wid = tid >> 5;
    int e = blockIdx.z;
    int off = g_offsets[e];
    int n = g_offsets[e + 1] - off;
    int t0 = blockIdx.y * 128;
    if (t0 >= n) return;
    int i0 = blockIdx.x * 32;
    const float* gwe = gw + (size_t)e * II * H;
    const float* uwe = uw + (size_t)e * II * H;
    int* sTok = (int*)(smem + 32);
    if (tid < 128) {
        int gm = t0 + tid;
        sTok[tid] = (gm < n) ? g_token_list[off + gm] : g_token_list[off];
    }
    __syncthreads();

    float C[2][4][4];
#pragma unroll
    for (int a = 0; a < 2; a++)
#pragma unroll
        for (int b = 0; b < 4; b++)
#pragma unroll
            for (int c = 0; c < 4; c++) C[a][b][c] = 0.f;

#define G1_ST(st) (sb + 1024 + (uint32_t)(st) * G1_STAGE)

#define G1_CPA(ch, st) do { \
    uint32_t bufA = G1_ST(st); \
    _Pragma("unroll") \
    for (int it = 0; it < 4; it++) { \
        int idx = tid + it * 256; \
        int row = idx >> 3, cc = idx & 7; \
        const __nv_bfloat16* src = ((cc < 4) ? g_xh : g_xl) \
            + (size_t)sTok[row] * H + (ch) * 32 + (cc & 3) * 8; \
        CP16(bufA + swz((uint32_t)(row * 128 + cc * 16)), src); \
    } \
    CPC(); \
} while (0)

#define G1_LDGW(ch, s) do { \
    int row = tid >> 2, q = tid & 3; \
    const float* src = ((row & 1) ? uwe : gwe) + (size_t)(i0 + (row >> 1)) * H + (ch) * 32 + q * 8; \
    wv[s][0] = *(const float4*)src; \
    wv[s][1] = *(const float4*)(src + 4); \
} while (0)

#define G1_STSW(s, st) do { \
    uint32_t bufB = G1_ST(st) + 16384; \
    int row = tid >> 2, q = tid & 3; \
    cvt8_sts(bufB + swz((uint32_t)(row * 128 + q * 16)), \
             bufB + swz((uint32_t)(row * 128 + 64 + q * 16)), \
             wv[s][0], wv[s][1]); \
} while (0)

    float4 wv[2][2];
    int wm0 = (wid & 3) * 32, wn0 = (wid >> 2) * 32;

    G1_CPA(0, 0); G1_LDGW(0, 0);
    G1_CPA(1, 1); G1_LDGW(1, 1);
    G1_STSW(0, 0);

    const int NC = H / 32;
    for (int c = 0; c < NC; c++) {
        int b = c & 1;
        if (c + 1 < NC) CPW(1); else CPW(0);
        __syncthreads();

        uint32_t bufA = G1_ST(b);
        uint32_t bufB = bufA + 16384;
#pragma unroll
        for (int ks = 0; ks < 2; ks++) {
            uint32_t ah[2][4], al[2][4];
            int krow = lane & 15, kc = ks * 16 + ((lane >> 4) & 1) * 8;
#pragma unroll
            for (int mt = 0; mt < 2; mt++) {
                uint32_t offh = (uint32_t)((wm0 + mt * 16 + krow) * 128 + kc * 2);
                ldm4(ah[mt], bufA + swz(offh));
                ldm4(al[mt], bufA + swz(offh + 64));
            }
#pragma unroll
            for (int nt2 = 0; nt2 < 2; nt2++) {
                int brow = wn0 + nt2 * 16 + ((lane >> 4) & 1) * 8 + (lane & 7);
                int bkc = ks * 16 + ((lane >> 3) & 1) * 8;
                uint32_t offb = (uint32_t)(brow * 128 + bkc * 2);
                uint32_t bh[4], bl[4];
                ldm4(bh, bufB + swz(offb));
                ldm4(bl, bufB + swz(offb + 64));
#pragma unroll
                for (int mt = 0; mt < 2; mt++) {
                    mma16(C[mt][nt2 * 2],     ah[mt], bh);
                    mma16(C[mt][nt2 * 2],     ah[mt], bl);
                    mma16(C[mt][nt2 * 2],     al[mt], bh);
                    mma16(C[mt][nt2 * 2 + 1], ah[mt], bh + 2);
                    mma16(C[mt][nt2 * 2 + 1], ah[mt], bl + 2);
                    mma16(C[mt][nt2 * 2 + 1], al[mt], bh + 2);
                }
            }
        }
        __syncthreads();
        if (c + 2 < NC) { G1_CPA(c + 2, b); G1_LDGW(c + 2, b); }
        if (c + 1 < NC) G1_STSW(1 - b, 1 - b);
    }

    // epilogue: even MMA col = gate, odd = up -> silu(g)*u -> bf16 hi/lo
    int tq = lane >> 2, tr = lane & 3;
#pragma unroll
    for (int mt = 0; mt < 2; mt++)
#pragma unroll
        for (int nt = 0; nt < 4; nt++) {
            int col = i0 + (wn0 >> 1) + nt * 4 + tr;
#pragma unroll
            for (int hh = 0; hh < 2; hh++) {
                int gm = t0 + wm0 + mt * 16 + tq + hh * 8;
                if (gm < n) {
                    float g = C[mt][nt][hh * 2], u = C[mt][nt][hh * 2 + 1];
                    float a = g / (1.f + __expf(-g)) * u;
                    __nv_bfloat16 h = __float2bfloat16_rn(a);
                    size_t ix = (size_t)(off + gm) * II + col;
                    g_ah[ix] = h;
                    g_al[ix] = __float2bfloat16_rn(a - __bfloat162float(h));
                }
            }
        }
}

// ---------- GEMM2: out[token] = act @ Wd^T ----------
// CTA: 128 tokens x 64 h-cols. 2 stages of 24KB (A 16KB + B 8KB). Warp tile 32x32.
#define G2_STAGE 24576
#define G2_SMEM (1024 + 2 * G2_STAGE)
__global__ __launch_bounds__(256, 2)
void gemm2_kernel(const float* __restrict__ dw, float* __restrict__ out) {
    extern __shared__ __align__(1024) char smem[];
    uint32_t sb = smem_u32(smem);
    int tid = threadIdx.x, lane = tid & 31, wid = tid >> 5;
    int e = blockIdx.z;
    int off = g_offsets[e];
    int n = g_offsets[e + 1] - off;
    int t0 = blockIdx.y * 128;
    if (t0 >= n) return;
    int h0 = blockIdx.x * 64;
    const float* dwe = dw + (size_t)e * H * II;
    int* sTok = (int*)(smem + 32);
    if (tid < 128) {
        int gm = t0 + tid;
        sTok[tid] = (gm < n) ? g_token_list[off + gm] : 0;
    }
    __syncthreads();

    float C[2][4][4];
#pragma unroll
    for (int a = 0; a < 2; a++)
#pragma unroll
        for (int b = 0; b < 4; b++)
#pragma unroll
            for (int c = 0; c < 4; c++) C[a][b][c] = 0.f;

#define G2_ST(st) (sb + 1024 + (uint32_t)(st) * G2_STAGE)

#define G2_CPA(ch, st) do { \
    uint32_t bufA = G2_ST(st); \
    _Pragma("unroll") \
    for (int it = 0; it < 4; it++) { \
        int idx = tid + it * 256; \
        int row = idx >> 3, cc = idx & 7; \
        const __nv_bfloat16* src = ((cc < 4) ? g_ah : g_al) \
            + (size_t)(off + t0 + row) * II + (ch) * 32 + (cc & 3) * 8; \
        CP16(bufA + swz((uint32_t)(row * 128 + cc * 16)), src); \
    } \
    CPC(); \
} while (0)

#define G2_LDGW(ch, s) do { \
    int row = tid >> 2, q = tid & 3; \
    const float* src = dwe + (size_t)(h0 + row) * II + (ch) * 32 + q * 8; \
    wv[s][0] = *(const float4*)src; \
    wv[s][1] = *(const float4*)(src + 4); \
} while (0)

#define G2_STSW(s, st) do { \
    uint32_t bufB = G2_ST(st) + 16384; \
    int row = tid >> 2, q = tid & 3; \
    cvt8_sts(bufB + swz((uint32_t)(row * 128 + q * 16)), \
             bufB + swz((uint32_t)(row * 128 + 64 + q * 16)), \
             wv[s][0], wv[s][1]); \
} while (0)

    float4 wv[2][2];
    int wm0 = (wid & 3) * 32, wn0 = (wid >> 2) * 32;

    G2_CPA(0, 0); G2_LDGW(0, 0);
    G2_CPA(1, 1); G2_LDGW(1, 1);
    G2_STSW(0, 0);

    const int NC = II / 32;
    for (int c = 0; c < NC; c++) {
        int b = c & 1;
        if (c + 1 < NC) CPW(1); else CPW(0);
        __syncthreads();

        uint32_t bufA = G2_ST(b);
        uint32_t bufB = bufA + 16384;
#pragma unroll
        for (int ks = 0; ks < 2; ks++) {
            uint32_t ah[2][4], al[2][4];
            int krow = lane & 15, kc = ks * 16 + ((lane >> 4) & 1) * 8;
#pragma unroll
            for (int mt = 0; mt < 2; mt++) {
                uint32_t offh = (uint32_t)((wm0 + mt * 16 + krow) * 128 + kc * 2);
                ldm4(ah[mt], bufA + swz(offh));
                ldm4(al[mt], bufA + swz(offh + 64));
            }
#pragma unroll
            for (int nt2 = 0; nt2 < 2; nt2++) {
                int brow = wn0 + nt2 * 16 + ((lane >> 4) & 1) * 8 + (lane & 7);
                int bkc = ks * 16 + ((lane >> 3) & 1) * 8;
                uint32_t offb = (uint32_t)(brow * 128 + bkc * 2);
                uint32_t bh[4], bl[4];
                ldm4(bh, bufB + swz(offb));
                ldm4(bl, bufB + swz(offb + 64));
#pragma unroll
                for (int mt = 0; mt < 2; mt++) {
                    mma16(C[mt][nt2 * 2],     ah[mt], bh);
                    mma16(C[mt][nt2 * 2],     ah[mt], bl);
                    mma16(C[mt][nt2 * 2],     al[mt], bh);
                    mma16(C[mt][nt2 * 2 + 1], ah[mt], bh + 2);
                    mma16(C[mt][nt2 * 2 + 1], ah[mt], bl + 2);
                    mma16(C[mt][nt2 * 2 + 1], al[mt], bh + 2);
                }
            }
        }
        __syncthreads();
        if (c + 2 < NC) { G2_CPA(c + 2, b); G2_LDGW(c + 2, b); }
        if (c + 1 < NC) G2_STSW(1 - b, 1 - b);
    }

    int tq = lane >> 2, tr = lane & 3;
#pragma unroll
    for (int mt = 0; mt < 2; mt++)
#pragma unroll
        for (int nt = 0; nt < 4; nt++) {
            int col = h0 + wn0 + nt * 8 + tr * 2;
#pragma unroll
            for (int hh = 0; hh < 2; hh++) {
                int m = wm0 + mt * 16 + tq + hh * 8;
                int gm = t0 + m;
                if (gm < n) {
                    int tok = sTok[m];
                    float2 o = make_float2(C[mt][nt][hh * 2], C[mt][nt][hh * 2 + 1]);
                    *(float2*)(out + (size_t)tok * H + col) = o;
                }
            }
        }
}

// ---------- launch ----------
extern "C" void kernel_launch(void* const* d_in, const int* in_sizes, int n_in,
                              void* d_out, int out_size) {
    const float* x  = (const float*)d_in[0];
    const float* rw = (const float*)d_in[1];
    const float* gw = (const float*)d_in[2];
    const float* uw = (const float*)d_in[3];
    const float* dw = (const float*)d_in[4];
    float* out = (float*)d_out;

    cudaFuncSetAttribute(gemm1_kernel, cudaFuncAttributeMaxDynamicSharedMemorySize, G1_SMEM);
    cudaFuncSetAttribute(gemm2_kernel, cudaFuncAttributeMaxDynamicSharedMemorySize, G2_SMEM);

    zero_kernel<<<1, 32>>>();
    router_kernel<<<T, 256>>>(x, rw);
    scan_scatter_kernel<<<1, 1024>>>();
    gemm1_kernel<<<dim3(II / 32, T / 128, E), 256, G1_SMEM>>>(gw, uw);
    gemm2_kernel<<<dim3(H / 64, T / 128, E), 256, G2_SMEM>>>(dw, out);
}

// round 13
// speedup vs baseline: 1.3215x; 1.1431x over previous
#include <cuda_runtime.h>
#include <cuda_fp16.h>
#include <cstdint>
#include <math.h>

#define T  1024
#define H  1024
#define II 2816
#define E  8

__device__ int   g_expert_id[T];
__device__ int   g_counts[E];
__device__ int   g_offsets[E + 1];
__device__ int   g_cursor[E];
__device__ int   g_token_list[T];
__device__ __half g_xh[(size_t)T * H];
__device__ __half g_xl[(size_t)T * H];
__device__ __half g_ah[(size_t)(T + 128) * II];
__device__ __half g_al[(size_t)(T + 128) * II];

// ---------- helpers ----------
__device__ __forceinline__ uint32_t smem_u32(const void* p) {
    uint32_t a;
    asm("{ .reg .u64 t; cvta.to.shared.u64 t, %1; cvt.u32.u64 %0, t; }" : "=r"(a) : "l"(p));
    return a;
}
__device__ __forceinline__ uint32_t swz(uint32_t o) { return o ^ ((o >> 3) & 0x70); }

#define CP16(d, s) asm volatile("cp.async.cg.shared.global [%0], [%1], 16;" :: "r"(d), "l"(s) : "memory")
#define CPC()      asm volatile("cp.async.commit_group;" ::: "memory")
#define CPW(n)     asm volatile("cp.async.wait_group %0;" :: "n"(n) : "memory")

__device__ __forceinline__ void ldm4(uint32_t* r, uint32_t a) {
    asm volatile("ldmatrix.sync.aligned.m8n8.x4.shared.b16 {%0,%1,%2,%3}, [%4];"
        : "=r"(r[0]), "=r"(r[1]), "=r"(r[2]), "=r"(r[3]) : "r"(a));
}
__device__ __forceinline__ void mma16(float* c, const uint32_t* a, const uint32_t* b) {
    asm volatile("mma.sync.aligned.m16n8k16.row.col.f32.f16.f16.f32 "
        "{%0,%1,%2,%3}, {%4,%5,%6,%7}, {%8,%9}, {%0,%1,%2,%3};"
        : "+f"(c[0]), "+f"(c[1]), "+f"(c[2]), "+f"(c[3])
        : "r"(a[0]), "r"(a[1]), "r"(a[2]), "r"(a[3]), "r"(b[0]), "r"(b[1]));
}
__device__ __forceinline__ uint32_t h2u(__half2 v) { return *(uint32_t*)&v; }
__device__ __forceinline__ void sts4u(uint32_t a, uint32_t x, uint32_t y, uint32_t z, uint32_t w) {
    asm volatile("st.shared.v4.b32 [%0], {%1, %2, %3, %4};"
        :: "r"(a), "r"(x), "r"(y), "r"(z), "r"(w) : "memory");
}
// 8 f32 -> 8 fp16 -> one 16B STS (weights, single precision pass)
__device__ __forceinline__ void cvt8h_sts(uint32_t d, float4 a, float4 b) {
    __half2 h0 = __floats2half2_rn(a.x, a.y);
    __half2 h1 = __floats2half2_rn(a.z, a.w);
    __half2 h2 = __floats2half2_rn(b.x, b.y);
    __half2 h3 = __floats2half2_rn(b.z, b.w);
    sts4u(d, h2u(h0), h2u(h1), h2u(h2), h2u(h3));
}

// ---------- routing (router + x split fused) ----------
__global__ void zero_kernel() {
    int i = threadIdx.x;
    if (i < E) { g_counts[i] = 0; g_cursor[i] = 0; }
}
__global__ void router_kernel(const float* __restrict__ x, const float* __restrict__ rw) {
    int t = blockIdx.x;
    __shared__ float sx[H];
    for (int i = threadIdx.x; i < H; i += blockDim.x) sx[i] = x[(size_t)t * H + i];
    __syncthreads();
    int w = threadIdx.x >> 5, l = threadIdx.x & 31;
    const float* wr = rw + (size_t)w * H;
    float acc = 0.f;
    for (int i = l; i < H; i += 32) acc += sx[i] * wr[i];
#pragma unroll
    for (int o = 16; o > 0; o >>= 1) acc += __shfl_xor_sync(0xffffffffu, acc, o);
    __shared__ float logits[E];
    if (l == 0) logits[w] = acc;
    __syncthreads();
    if (threadIdx.x == 0) {
        int best = 0; float bv = logits[0];
#pragma unroll
        for (int e = 1; e < E; e++) if (logits[e] > bv) { bv = logits[e]; best = e; }
        g_expert_id[t] = best;
        atomicAdd(&g_counts[best], 1);
    }
    int i = threadIdx.x * 4;
    float4 v = *(float4*)&sx[i];
    __half2 h01 = __floats2half2_rn(v.x, v.y);
    __half2 h23 = __floats2half2_rn(v.z, v.w);
    size_t base = (size_t)t * H + i;
    *(__half2*)(g_xh + base) = h01;
    *(__half2*)(g_xh + base + 2) = h23;
    __half2 l01 = __floats2half2_rn(v.x - __half2float(h01.x), v.y - __half2float(h01.y));
    __half2 l23 = __floats2half2_rn(v.z - __half2float(h23.x), v.w - __half2float(h23.y));
    *(__half2*)(g_xl + base) = l01;
    *(__half2*)(g_xl + base + 2) = l23;
}
__global__ void scan_scatter_kernel() {
    if (threadIdx.x == 0) {
        int o = 0;
        for (int e = 0; e < E; e++) { g_offsets[e] = o; o += g_counts[e]; }
        g_offsets[E] = o;
    }
    __syncthreads();
    int t = threadIdx.x;
    int e = g_expert_id[t];
    g_token_list[g_offsets[e] + atomicAdd(&g_cursor[e], 1)] = t;
}

// ---------- GEMM1: act = silu(X Wg^T) * (X Wu^T) ----------
// CTA: 128 tokens x 32 i-cols (gate/up rows interleaved -> MMA-N = 64).
// 2 smem stages of 24KB (A 16KB hi|lo + B 8KB, lo-half of B unused).
#define G1_STAGE 24576
#define G1_SMEM (1024 + 2 * G1_STAGE)
__global__ __launch_bounds__(256, 2)
void gemm1_kernel(const float* __restrict__ gw, const float* __restrict__ uw) {
    extern __shared__ __align__(1024) char smem[];
    uint32_t sb = smem_u32(smem);
    int tid = threadIdx.x, lane = tid & 31, wid = tid >> 5;
    int e = blockIdx.z;
    int off = g_offsets[e];
    int n = g_offsets[e + 1] - off;
    int t0 = blockIdx.y * 128;
    if (t0 >= n) return;
    int i0 = blockIdx.x * 32;
    const float* gwe = gw + (size_t)e * II * H;
    const float* uwe = uw + (size_t)e * II * H;
    int* sTok = (int*)(smem + 32);
    if (tid < 128) {
        int gm = t0 + tid;
        sTok[tid] = (gm < n) ? g_token_list[off + gm] : g_token_list[off];
    }
    __syncthreads();

    float C[2][4][4];
#pragma unroll
    for (int a = 0; a < 2; a++)
#pragma unroll
        for (int b = 0; b < 4; b++)
#pragma unroll
            for (int c = 0; c < 4; c++) C[a][b][c] = 0.f;

#define G1_ST(st) (sb + 1024 + (uint32_t)(st) * G1_STAGE)

#define G1_CPA(ch, st) do { \
    uint32_t bufA = G1_ST(st); \
    _Pragma("unroll") \
    for (int it = 0; it < 4; it++) { \
        int idx = tid + it * 256; \
        int row = idx >> 3, cc = idx & 7; \
        const __half* src = ((cc < 4) ? g_xh : g_xl) \
            + (size_t)sTok[row] * H + (ch) * 32 + (cc & 3) * 8; \
        CP16(bufA + swz((uint32_t)(row * 128 + cc * 16)), src); \
    } \
    CPC(); \
} while (0)

#define G1_LDGW(ch, s) do { \
    int row = tid >> 2, q = tid & 3; \
    const float* src = ((row & 1) ? uwe : gwe) + (size_t)(i0 + (row >> 1)) * H + (ch) * 32 + q * 8; \
    wv[s][0] = *(const float4*)src; \
    wv[s][1] = *(const float4*)(src + 4); \
} while (0)

#define G1_STSW(s, st) do { \
    uint32_t bufB = G1_ST(st) + 16384; \
    int row = tid >> 2, q = tid & 3; \
    cvt8h_sts(bufB + swz((uint32_t)(row * 128 + q * 16)), wv[s][0], wv[s][1]); \
} while (0)

    float4 wv[2][2];
    int wm0 = (wid & 3) * 32, wn0 = (wid >> 2) * 32;

    G1_CPA(0, 0); G1_LDGW(0, 0);
    G1_CPA(1, 1); G1_LDGW(1, 1);
    G1_STSW(0, 0);

    const int NC = H / 32;
    for (int c = 0; c < NC; c++) {
        int b = c & 1;
        if (c + 1 < NC) CPW(1); else CPW(0);
        __syncthreads();

        uint32_t bufA = G1_ST(b);
        uint32_t bufB = bufA + 16384;
#pragma unroll
        for (int ks = 0; ks < 2; ks++) {
            uint32_t ah[2][4], al[2][4];
            int krow = lane & 15, kc = ks * 16 + ((lane >> 4) & 1) * 8;
#pragma unroll
            for (int mt = 0; mt < 2; mt++) {
                uint32_t offh = (uint32_t)((wm0 + mt * 16 + krow) * 128 + kc * 2);
                ldm4(ah[mt], bufA + swz(offh));
                ldm4(al[mt], bufA + swz(offh + 64));
            }
#pragma unroll
            for (int nt2 = 0; nt2 < 2; nt2++) {
                int brow = wn0 + nt2 * 16 + ((lane >> 4) & 1) * 8 + (lane & 7);
                int bkc = ks * 16 + ((lane >> 3) & 1) * 8;
                uint32_t offb = (uint32_t)(brow * 128 + bkc * 2);
                uint32_t bh[4];
                ldm4(bh, bufB + swz(offb));
#pragma unroll
                for (int mt = 0; mt < 2; mt++) {
                    mma16(C[mt][nt2 * 2],     ah[mt], bh);
                    mma16(C[mt][nt2 * 2 + 1], ah[mt], bh + 2);
                    mma16(C[mt][nt2 * 2],     al[mt], bh);
                    mma16(C[mt][nt2 * 2 + 1], al[mt], bh + 2);
                }
            }
        }
        __syncthreads();
        if (c + 2 < NC) { G1_CPA(c + 2, b); G1_LDGW(c + 2, b); }
        if (c + 1 < NC) G1_STSW(1 - b, 1 - b);
    }

    // epilogue: even MMA col = gate, odd = up -> silu(g)*u -> fp16 hi/lo
    int tq = lane >> 2, tr = lane & 3;
#pragma unroll
    for (int mt = 0; mt < 2; mt++)
#pragma unroll
        for (int nt = 0; nt < 4; nt++) {
            int col = i0 + (wn0 >> 1) + nt * 4 + tr;
#pragma unroll
            for (int hh = 0; hh < 2; hh++) {
                int gm = t0 + wm0 + mt * 16 + tq + hh * 8;
                if (gm < n) {
                    float g = C[mt][nt][hh * 2], u = C[mt][nt][hh * 2 + 1];
                    float a = g / (1.f + __expf(-g)) * u;
                    __half h = __float2half_rn(a);
                    size_t ix = (size_t)(off + gm) * II + col;
                    g_ah[ix] = h;
                    g_al[ix] = __float2half_rn(a - __half2float(h));
                }
            }
        }
}

// ---------- GEMM2: out[token] = act @ Wd^T ----------
// CTA: 128 tokens x 64 h-cols. 2 stages of 24KB (A 16KB hi|lo + B 8KB half-used).
#define G2_STAGE 24576
#define G2_SMEM (1024 + 2 * G2_STAGE)
__global__ __launch_bounds__(256, 2)
void gemm2_kernel(const float* __restrict__ dw, float* __restrict__ out) {
    extern __shared__ __align__(1024) char smem[];
    uint32_t sb = smem_u32(smem);
    int tid = threadIdx.x, lane = tid & 31, wid = tid >> 5;
    int e = blockIdx.z;
    int off = g_offsets[e];
    int n = g_offsets[e + 1] - off;
    int t0 = blockIdx.y * 128;
    if (t0 >= n) return;
    int h0 = blockIdx.x * 64;
    const float* dwe = dw + (size_t)e * H * II;
    int* sTok = (int*)(smem + 32);
    if (tid < 128) {
        int gm = t0 + tid;
        sTok[tid] = (gm < n) ? g_token_list[off + gm] : 0;
    }
    __syncthreads();

    float C[2][4][4];
#pragma unroll
    for (int a = 0; a < 2; a++)
#pragma unroll
        for (int b = 0; b < 4; b++)
#pragma unroll
            for (int c = 0; c < 4; c++) C[a][b][c] = 0.f;

#define G2_ST(st) (sb + 1024 + (uint32_t)(st) * G2_STAGE)

#define G2_CPA(ch, st) do { \
    uint32_t bufA = G2_ST(st); \
    _Pragma("unroll") \
    for (int it = 0; it < 4; it++) { \
        int idx = tid + it * 256; \
        int row = idx >> 3, cc = idx & 7; \
        const __half* src = ((cc < 4) ? g_ah : g_al) \
            + (size_t)(off + t0 + row) * II + (ch) * 32 + (cc & 3) * 8; \
        CP16(bufA + swz((uint32_t)(row * 128 + cc * 16)), src); \
    } \
    CPC(); \
} while (0)

#define G2_LDGW(ch, s) do { \
    int row = tid >> 2, q = tid & 3; \
    const float* src = dwe + (size_t)(h0 + row) * II + (ch) * 32 + q * 8; \
    wv[s][0] = *(const float4*)src; \
    wv[s][1] = *(const float4*)(src + 4); \
} while (0)

#define G2_STSW(s, st) do { \
    uint32_t bufB = G2_ST(st) + 16384; \
    int row = tid >> 2, q = tid & 3; \
    cvt8h_sts(bufB + swz((uint32_t)(row * 128 + q * 16)), wv[s][0], wv[s][1]); \
} while (0)

    float4 wv[2][2];
    int wm0 = (wid & 3) * 32, wn0 = (wid >> 2) * 32;

    G2_CPA(0, 0); G2_LDGW(0, 0);
    G2_CPA(1, 1); G2_LDGW(1, 1);
    G2_STSW(0, 0);

    const int NC = II / 32;
    for (int c = 0; c < NC; c++) {
        int b = c & 1;
        if (c + 1 < NC) CPW(1); else CPW(0);
        __syncthreads();

        uint32_t bufA = G2_ST(b);
        uint32_t bufB = bufA + 16384;
#pragma unroll
        for (int ks = 0; ks < 2; ks++) {
            uint32_t ah[2][4], al[2][4];
            int krow = lane & 15, kc = ks * 16 + ((lane >> 4) & 1) * 8;
#pragma unroll
            for (int mt = 0; mt < 2; mt++) {
                uint32_t offh = (uint32_t)((wm0 + mt * 16 + krow) * 128 + kc * 2);
                ldm4(ah[mt], bufA + swz(offh));
                ldm4(al[mt], bufA + swz(offh + 64));
            }
#pragma unroll
            for (int nt2 = 0; nt2 < 2; nt2++) {
                int brow = wn0 + nt2 * 16 + ((lane >> 4) & 1) * 8 + (lane & 7);
                int bkc = ks * 16 + ((lane >> 3) & 1) * 8;
                uint32_t offb = (uint32_t)(brow * 128 + bkc * 2);
                uint32_t bh[4];
                ldm4(bh, bufB + swz(offb));
#pragma unroll
                for (int mt = 0; mt < 2; mt++) {
                    mma16(C[mt][nt2 * 2],     ah[mt], bh);
                    mma16(C[mt][nt2 * 2 + 1], ah[mt], bh + 2);
                    mma16(C[mt][nt2 * 2],     al[mt], bh);
                    mma16(C[mt][nt2 * 2 + 1], al[mt], bh + 2);
                }
            }
        }
        __syncthreads();
        if (c + 2 < NC) { G2_CPA(c + 2, b); G2_LDGW(c + 2, b); }
        if (c + 1 < NC) G2_STSW(1 - b, 1 - b);
    }

    int tq = lane >> 2, tr = lane & 3;
#pragma unroll
    for (int mt = 0; mt < 2; mt++)
#pragma unroll
        for (int nt = 0; nt < 4; nt++) {
            int col = h0 + wn0 + nt * 8 + tr * 2;
#pragma unroll
            for (int hh = 0; hh < 2; hh++) {
                int m = wm0 + mt * 16 + tq + hh * 8;
                int gm = t0 + m;
                if (gm < n) {
                    int tok = sTok[m];
                    float2 o = make_float2(C[mt][nt][hh * 2], C[mt][nt][hh * 2 + 1]);
                    *(float2*)(out + (size_t)tok * H + col) = o;
                }
            }
        }
}

// ---------- launch ----------
extern "C" void kernel_launch(void* const* d_in, const int* in_sizes, int n_in,
                              void* d_out, int out_size) {
    const float* x  = (const float*)d_in[0];
    const float* rw = (const float*)d_in[1];
    const float* gw = (const float*)d_in[2];
    const float* uw = (const float*)d_in[3];
    const float* dw = (const float*)d_in[4];
    float* out = (float*)d_out;

    cudaFuncSetAttribute(gemm1_kernel, cudaFuncAttributeMaxDynamicSharedMemorySize, G1_SMEM);
    cudaFuncSetAttribute(gemm2_kernel, cudaFuncAttributeMaxDynamicSharedMemorySize, G2_SMEM);

    zero_kernel<<<1, 32>>>();
    router_kernel<<<T, 256>>>(x, rw);
    scan_scatter_kernel<<<1, 1024>>>();
    gemm1_kernel<<<dim3(II / 32, T / 128, E), 256, G1_SMEM>>>(gw, uw);
    gemm2_kernel<<<dim3(H / 64, T / 128, E), 256, G2_SMEM>>>(dw, out);
}